// round 9
// baseline (speedup 1.0000x reference)
#include <cuda_runtime.h>

// ---------------------------------------------------------------------------
// DecGreenNet_product_CP3 — single fused kernel, role-split blocks:
//   A-blocks  (bid 0..191)  : branch partials  sum_n y_n tanh(q_n w_j + b_j)
//   V-blocks  (bid 192..319): reduce -> s_br -> rhs -> c ; 4 rows of v each
//   C-blocks  (bid 320..)   : out[i] = c + sum_h v[h] tanh(x_i.W[:,h]+b[h])
// Global-flag pipeline (cntA -> flagV) replaces 3 kernel launches.
// C uses hybrid tanh: odd h via FMA Pade[7/6]+rcp (8 MUFU-cyc), even h via
// tanh.approx (16 MUFU-cyc) — breaks the rt16 MUFU ceiling C was pinned at.
// ---------------------------------------------------------------------------

#define PI_F 3.14159265358979323846f
#define NUM_V 128

__device__ float g_part[3][64][128];
__device__ float g_party[3][64];
__device__ float g_v[512];
__device__ float g_c;
__device__ int   g_cntA;
__device__ int   g_cntV;
__device__ int   g_flagV;
__device__ int   g_cntEnd;

__device__ __forceinline__ float tanh_mufu(float x) {
    float y;
    asm("tanh.approx.f32 %0, %1;" : "=f"(y) : "f"(x));
    return y;
}
__device__ __forceinline__ float frcp(float x) {
    float y;
    asm("rcp.approx.f32 %0, %1;" : "=f"(y) : "f"(x));
    return y;
}
// accurate tanh (~1e-6) for the branch path (cancellation-sensitive sums)
__device__ __forceinline__ float tanh_acc(float z) {
    float e = __expf(2.0f * z);
    return 1.0f - __fdividef(2.0f, e + 1.0f);
}
// FMA-pipe tanh: Pade[7/6], clamp +-4.97, abs err <= ~1.5e-4
__device__ __forceinline__ float tanh_fma(float z) {
    const float zc = fminf(fmaxf(z, -4.97f), 4.97f);
    const float t  = zc * zc;
    const float p  = zc * fmaf(t, fmaf(t, fmaf(t, 1.0f, 378.0f), 17325.0f), 135135.0f);
    const float q  = fmaf(t, fmaf(t, fmaf(t, 28.0f, 3150.0f), 62370.0f), 135135.0f);
    return p * frcp(q);
}

__global__ void __launch_bounds__(512) mega(
        const float* __restrict__ X,
        const float* __restrict__ eq,
        const float* __restrict__ q0, const float* __restrict__ q1,
        const float* __restrict__ q2,
        const float* __restrict__ Wx1, const float* __restrict__ bx1,
        const float* __restrict__ Wx2, const float* __restrict__ bx2,
        const float* __restrict__ w0, const float* __restrict__ c0,
        const float* __restrict__ W02, const float* __restrict__ B02,
        const float* __restrict__ w1, const float* __restrict__ c1,
        const float* __restrict__ W12, const float* __restrict__ B12,
        const float* __restrict__ w2, const float* __restrict__ c2,
        const float* __restrict__ W22, const float* __restrict__ B22,
        float* __restrict__ out, int Bn, int nchunk)
{
    const int bid  = blockIdx.x;
    const int tid  = threadIdx.x;
    const int lane = tid & 31;
    const int w    = tid >> 5;
    const int numA = 3 * nchunk;            // 192

    // =================== A role: branch partials =========================
    if (bid < numA) {
        const int br    = bid / nchunk;
        const int chunk = bid - br * nchunk;
        const float* qx = (br == 0) ? q0 : ((br == 1) ? q1 : q2);
        const float* W1 = (br == 0) ? w0 : ((br == 1) ? w1 : w2);
        const float* B1 = (br == 0) ? c0 : ((br == 1) ? c1 : c2);

        __shared__ float pacc[4][128];
        __shared__ float syp[4];

        const int jgrp = w & 3;             // j-range quarter
        const int ngrp = w >> 2;            // node-group (32 nodes)
        const int j    = (jgrp << 5) + lane;

        const float pe = PI_F * eq[0];
        const float q  = qx[chunk * 128 + ngrp * 32 + lane];
        const float y  = sinf(pe * q);

        const float wj = W1[j];
        const float bj = B1[j];
        float acc = 0.f;
#pragma unroll
        for (int k = 0; k < 32; k++) {
            const float qk = __shfl_sync(0xffffffffu, q, k);
            const float yk = __shfl_sync(0xffffffffu, y, k);
            acc = fmaf(yk, tanh_acc(fmaf(qk, wj, bj)), acc);
        }
        pacc[ngrp][j] = acc;

        if (jgrp == 0) {                    // warps 0,4,8,12 reduce sum_y
            float s = y;
#pragma unroll
            for (int o = 16; o; o >>= 1) s += __shfl_xor_sync(0xffffffffu, s, o);
            if (lane == 0) syp[ngrp] = s;
        }
        __syncthreads();

        if (tid < 128) {
            g_part[br][chunk][tid] =
                pacc[0][tid] + pacc[1][tid] + pacc[2][tid] + pacc[3][tid];
        } else if (tid == 128) {
            g_party[br][chunk] = syp[0] + syp[1] + syp[2] + syp[3];
        }
        __syncthreads();
        __threadfence();
        if (tid == 0) atomicAdd(&g_cntA, 1);
    }
    // =================== V role: rhs + 4 rows of v =======================
    else if (bid < numA + NUM_V) {
        const int vid = bid - numA;

        __shared__ float wh[3][128];
        __shared__ float sumy[3];
        __shared__ float s_sh[3][128];
        __shared__ __align__(16) float rsh[512];
        __shared__ float red[512];

        if (tid == 0) {
            while (*(volatile int*)&g_cntA != numA) __nanosleep(64);
        }
        __syncthreads();
        __threadfence();

        if (tid < 384) {
            const int br = tid >> 7, j = tid & 127;
            float a = 0.f;
#pragma unroll 16
            for (int blk = 0; blk < 64; blk++) a += g_part[br][blk][j];
            wh[br][j] = a;
        } else if (tid < 387) {
            const int br = tid - 384;
            float s = 0.f;
#pragma unroll 16
            for (int blk = 0; blk < 64; blk++) s += g_party[br][blk];
            sumy[br] = s;
        }
        __syncthreads();

        if (tid < 384) {
            const int br = tid >> 7, col = tid & 127;
            const float* W2 = (br == 0) ? W02 : ((br == 1) ? W12 : W22);
            const float* B2 = (br == 0) ? B02 : ((br == 1) ? B12 : B22);
            float a = sumy[br] * B2[col];
#pragma unroll 16
            for (int j = 0; j < 128; j++) a = fmaf(wh[br][j], W2[j * 128 + col], a);
            s_sh[br][col] = a;              // col = b*16 + x
        }
        __syncthreads();

        {
            const int b = tid >> 6, d = (tid >> 3) & 7, f = tid & 7;
            float r = 0.f;
#pragma unroll
            for (int x = 0; x < 16; x++)
                r += s_sh[0][b * 16 + x] * s_sh[1][d * 16 + x] * s_sh[2][f * 16 + x];
            rsh[tid] = r;
            red[tid] = bx2[tid] * r;
        }
        __syncthreads();
        for (int off = 256; off > 0; off >>= 1) {
            if (tid < off) red[tid] += red[tid + off];
            __syncthreads();
        }
        if (tid == 0) g_c = red[0];         // same value from every V block

        // 4 rows of v, warp per row
        if (w < 4) {
            const int h = vid * 4 + w;
            const float4* row4 = (const float4*)(Wx2 + h * 512);
            const float4* r4   = (const float4*)rsh;
            float a = 0.f;
#pragma unroll
            for (int k = lane; k < 128; k += 32) {
                const float4 wv = row4[k];
                const float4 rv = r4[k];
                a = fmaf(wv.x, rv.x, fmaf(wv.y, rv.y,
                    fmaf(wv.z, rv.z, fmaf(wv.w, rv.w, a))));
            }
#pragma unroll
            for (int o = 16; o; o >>= 1) a += __shfl_xor_sync(0xffffffffu, a, o);
            if (lane == 0) g_v[h] = a;
        }
        __syncthreads();
        __threadfence();
        if (tid == 0) {
            const int r = atomicAdd(&g_cntV, 1);
            if (r == NUM_V - 1) atomicExch(&g_flagV, 1);
        }
    }
    // =================== C role: main batch ==============================
    else {
        const int cid = bid - (numA + NUM_V);

        __shared__ float4 wt[512];
        __shared__ float  vs[512];
        __shared__ __align__(16) float pp[16][128];

        // weight preload is independent of the pipeline — do it while waiting
        wt[tid] = make_float4(Wx1[tid], Wx1[512 + tid], Wx1[1024 + tid], bx1[tid]);

        if (tid == 0) {
            while (*(volatile int*)&g_flagV == 0) __nanosleep(64);
        }
        __syncthreads();
        __threadfence();
        vs[tid] = g_v[tid];
        __syncthreads();

        const int h0 = w << 5;              // 32 h per warp
        const int r0 = cid * 128 + lane * 4;

        float xv[12];
        if (r0 + 3 < Bn) {
            const float4* xp = (const float4*)(X + r0 * 3);  // 16B-aligned
#pragma unroll
            for (int qq = 0; qq < 3; qq++) {
                const float4 v4 = xp[qq];
                xv[qq * 4 + 0] = v4.x; xv[qq * 4 + 1] = v4.y;
                xv[qq * 4 + 2] = v4.z; xv[qq * 4 + 3] = v4.w;
            }
        } else {
#pragma unroll
            for (int qq = 0; qq < 12; qq++) {
                const int gi = r0 * 3 + qq;
                xv[qq] = (gi < Bn * 3) ? X[gi] : 0.f;
            }
        }

        float a0 = 0.f, a1 = 0.f, a2 = 0.f, a3 = 0.f;
#pragma unroll 4
        for (int hh = 0; hh < 32; hh += 2) {
            {   // even h: MUFU tanh
                const float4 wv = wt[h0 + hh];
                const float  vv = vs[h0 + hh];
                const float z0 = fmaf(xv[2],  wv.z, fmaf(xv[1],  wv.y, fmaf(xv[0], wv.x, wv.w)));
                const float z1 = fmaf(xv[5],  wv.z, fmaf(xv[4],  wv.y, fmaf(xv[3], wv.x, wv.w)));
                const float z2 = fmaf(xv[8],  wv.z, fmaf(xv[7],  wv.y, fmaf(xv[6], wv.x, wv.w)));
                const float z3 = fmaf(xv[11], wv.z, fmaf(xv[10], wv.y, fmaf(xv[9], wv.x, wv.w)));
                a0 = fmaf(vv, tanh_mufu(z0), a0);
                a1 = fmaf(vv, tanh_mufu(z1), a1);
                a2 = fmaf(vv, tanh_mufu(z2), a2);
                a3 = fmaf(vv, tanh_mufu(z3), a3);
            }
            {   // odd h: FMA-pipe Pade tanh (rcp only on MUFU)
                const float4 wv = wt[h0 + hh + 1];
                const float  vv = vs[h0 + hh + 1];
                const float z0 = fmaf(xv[2],  wv.z, fmaf(xv[1],  wv.y, fmaf(xv[0], wv.x, wv.w)));
                const float z1 = fmaf(xv[5],  wv.z, fmaf(xv[4],  wv.y, fmaf(xv[3], wv.x, wv.w)));
                const float z2 = fmaf(xv[8],  wv.z, fmaf(xv[7],  wv.y, fmaf(xv[6], wv.x, wv.w)));
                const float z3 = fmaf(xv[11], wv.z, fmaf(xv[10], wv.y, fmaf(xv[9], wv.x, wv.w)));
                a0 = fmaf(vv, tanh_fma(z0), a0);
                a1 = fmaf(vv, tanh_fma(z1), a1);
                a2 = fmaf(vv, tanh_fma(z2), a2);
                a3 = fmaf(vv, tanh_fma(z3), a3);
            }
        }

        *((float4*)&pp[w][lane * 4]) = make_float4(a0, a1, a2, a3);
        __syncthreads();

        if (tid < 128) {
            float s = g_c;
#pragma unroll
            for (int w2 = 0; w2 < 16; w2++) s += pp[w2][tid];
            const int oi = cid * 128 + tid;
            if (oi < Bn) out[oi] = s;
        }
        __syncthreads();
    }

    // =================== epilogue: reset counters for next replay ========
    if (tid == 0) {
        const int d = atomicAdd(&g_cntEnd, 1);
        if (d == (int)gridDim.x - 1) {
            *(volatile int*)&g_cntA   = 0;
            *(volatile int*)&g_cntV   = 0;
            *(volatile int*)&g_flagV  = 0;
            *(volatile int*)&g_cntEnd = 0;
        }
    }
}

// ---------------------------------------------------------------------------
extern "C" void kernel_launch(void* const* d_in, const int* in_sizes, int n_in,
                              void* d_out, int out_size)
{
    const float* input = (const float*)d_in[0];
    const float* eq    = (const float*)d_in[1];
    const float* q0    = (const float*)d_in[2];
    const float* q1    = (const float*)d_in[3];
    const float* q2    = (const float*)d_in[4];
    const float* Wx1   = (const float*)d_in[5];
    const float* bx1   = (const float*)d_in[6];
    const float* Wx2   = (const float*)d_in[7];
    const float* bx2   = (const float*)d_in[8];
    const float* Wq01  = (const float*)d_in[9];
    const float* bq01  = (const float*)d_in[10];
    const float* Wq02  = (const float*)d_in[11];
    const float* bq02  = (const float*)d_in[12];
    const float* Wq11  = (const float*)d_in[13];
    const float* bq11  = (const float*)d_in[14];
    const float* Wq12  = (const float*)d_in[15];
    const float* bq12  = (const float*)d_in[16];
    const float* Wq21  = (const float*)d_in[17];
    const float* bq21  = (const float*)d_in[18];
    const float* Wq22  = (const float*)d_in[19];
    const float* bq22  = (const float*)d_in[20];

    const int N      = in_sizes[2];         // 8192
    const int Bn     = in_sizes[0] / 3;     // 65536
    const int nchunk = N / 128;             // 64
    const int numA   = 3 * nchunk;          // 192
    const int numC   = (Bn + 127) / 128;    // 512
    const int grid   = numA + NUM_V + numC; // 832

    mega<<<grid, 512>>>(input, eq, q0, q1, q2,
                        Wx1, bx1, Wx2, bx2,
                        Wq01, bq01, Wq02, bq02,
                        Wq11, bq11, Wq12, bq12,
                        Wq21, bq21, Wq22, bq22,
                        (float*)d_out, Bn, nchunk);
}

// round 10
// speedup vs baseline: 1.3433x; 1.3433x over previous
#include <cuda_runtime.h>

// ---------------------------------------------------------------------------
// DecGreenNet_product_CP3 — algebraically collapsed:
//   out[i] = c + sum_h v[h] * tanh(x_i . Wx1[:,h] + bx1[h])
//   s_br = (sum_n y_n h_n) @ Wq2_br + (sum_n y_n) * bq2_br
//   rhs[b,d,f] = sum_x s0[b,x] s1[d,x] s2[f,x];  v = Wx2 @ rhs;  c = bx2 . rhs
// kernelC now uses tanh.approx.f16x2: 2 tanh per MUFU op (rt16) — halves the
// MUFU ceiling the fp32 version was pinned at since R5.
// ---------------------------------------------------------------------------

#define PI_F 3.14159265358979323846f

__device__ float g_part[3][128][128];  // per-branch per-chunk weighted-tanh sums
__device__ float g_party[3][128];      // per-branch per-chunk sum of y
__device__ float g_v[512];
__device__ float g_c;

// accurate tanh (~1e-6 abs err) — branch path (cancellation-sensitive sums)
__device__ __forceinline__ float tanh_acc(float z) {
    float e = __expf(2.0f * z);
    return 1.0f - __fdividef(2.0f, e + 1.0f);
}

// packed half tanh: 2 results per MUFU op.  za -> ta, zb -> tb.
// cvt.rn.f16x2.f32 d,a,b packs a into the HIGH half, b into the LOW half.
__device__ __forceinline__ void tanh2(float za, float zb, float& ta, float& tb) {
    asm("{\n\t"
        ".reg .b32 p;\n\t"
        ".reg .b16 l, h;\n\t"
        "cvt.rn.f16x2.f32 p, %3, %2;\n\t"   // high=zb, low=za
        "tanh.approx.f16x2 p, p;\n\t"
        "mov.b32 {l, h}, p;\n\t"
        "cvt.f32.f16 %0, l;\n\t"
        "cvt.f32.f16 %1, h;\n\t"
        "}" : "=f"(ta), "=f"(tb) : "f"(za), "f"(zb));
}

// ---------------------------------------------------------------------------
// Kernel A: branch partials.  grid (128, 3) x 512 threads; chunk = 64 nodes.
// No pre-loop barrier: each warp loads 16 nodes into lanes, broadcasts by shfl.
// ---------------------------------------------------------------------------
__global__ void __launch_bounds__(512) kernelA(
        const float* __restrict__ q0, const float* __restrict__ q1,
        const float* __restrict__ q2,
        const float* __restrict__ w0, const float* __restrict__ w1,
        const float* __restrict__ w2,
        const float* __restrict__ c0, const float* __restrict__ c1,
        const float* __restrict__ c2,
        const float* __restrict__ eq)
{
    const int br = blockIdx.y;
    const float* qx = (br == 0) ? q0 : ((br == 1) ? q1 : q2);
    const float* W1 = (br == 0) ? w0 : ((br == 1) ? w1 : w2);
    const float* B1 = (br == 0) ? c0 : ((br == 1) ? c1 : c2);

    __shared__ float pacc[4][128];
    __shared__ float sy64[64];

    const int t    = threadIdx.x;
    const int lane = t & 31;
    const int w    = t >> 5;          // 0..15
    const int grp  = w >> 2;          // 0..3 -> which 16 nodes
    const int j    = ((w & 3) << 5) + lane;

    const float pe = PI_F * eq[0];

    float q = 0.f, y = 0.f;
    if (lane < 16) {
        q = qx[blockIdx.x * 64 + grp * 16 + lane];
        y = sinf(pe * q);
        if ((w & 3) == 0) sy64[grp * 16 + lane] = y;   // for sum_y only
    }

    const float wj = W1[j];
    const float bj = B1[j];
    float acc = 0.f;
#pragma unroll
    for (int k = 0; k < 16; k++) {
        const float qk = __shfl_sync(0xffffffffu, q, k);
        const float yk = __shfl_sync(0xffffffffu, y, k);
        acc = fmaf(yk, tanh_acc(fmaf(qk, wj, bj)), acc);
    }
    pacc[grp][j] = acc;
    __syncthreads();

    if (t < 128) {
        g_part[br][blockIdx.x][t] =
            pacc[0][t] + pacc[1][t] + pacc[2][t] + pacc[3][t];
    } else if (w == 4) {              // one warp reduces sum_y
        float s = sy64[lane] + sy64[lane + 32];
#pragma unroll
        for (int o = 16; o; o >>= 1) s += __shfl_xor_sync(0xffffffffu, s, o);
        if (lane == 0) g_party[br][blockIdx.x] = s;
    }
}

// ---------------------------------------------------------------------------
// Kernel BV: grid 64 x 512.  Every block redundantly computes the tiny
// phases 1-3 (identical deterministic results), then its own 8 rows of
// v = Wx2 @ rhs.  Keeps the 1MB Wx2 stream spread over 64 SMs.
// ---------------------------------------------------------------------------
__global__ void __launch_bounds__(512) kernelBV(
        const float* __restrict__ Wq02, const float* __restrict__ bq02,
        const float* __restrict__ Wq12, const float* __restrict__ bq12,
        const float* __restrict__ Wq22, const float* __restrict__ bq22,
        const float* __restrict__ bx2,  const float* __restrict__ Wx2)
{
    __shared__ float wh[3][128];
    __shared__ float sumy[3];
    __shared__ float s_sh[3][128];
    __shared__ __align__(16) float rsh[512];
    __shared__ float red[512];

    const int t = threadIdx.x;

    // phase 1: reduce per-chunk partials (128 chunks)
    if (t < 384) {
        const int br = t >> 7, j = t & 127;
        float a = 0.f;
#pragma unroll 16
        for (int blk = 0; blk < 128; blk++) a += g_part[br][blk][j];
        wh[br][j] = a;
    } else if (t < 387) {
        const int br = t - 384;
        float s = 0.f;
#pragma unroll 16
        for (int blk = 0; blk < 128; blk++) s += g_party[br][blk];
        sumy[br] = s;
    }
    __syncthreads();

    // phase 2: s_br = wh_br @ Wq2_br + sumy_br * bq2_br (coalesced columns)
    if (t < 384) {
        const int br = t >> 7, c = t & 127;
        const float* W2 = (br == 0) ? Wq02 : ((br == 1) ? Wq12 : Wq22);
        const float* B2 = (br == 0) ? bq02 : ((br == 1) ? bq12 : bq22);
        float a = sumy[br] * B2[c];
#pragma unroll 16
        for (int j = 0; j < 128; j++) a = fmaf(wh[br][j], W2[j * 128 + c], a);
        s_sh[br][c] = a;                   // c = b*16 + x
    }
    __syncthreads();

    // phase 3: rhs + c
    if (t < 512) {
        const int b = t >> 6, d = (t >> 3) & 7, f = t & 7;
        float r = 0.f;
#pragma unroll
        for (int x = 0; x < 16; x++)
            r += s_sh[0][b * 16 + x] * s_sh[1][d * 16 + x] * s_sh[2][f * 16 + x];
        rsh[t] = r;
        red[t] = bx2[t] * r;
    }
    __syncthreads();
    for (int off = 256; off > 0; off >>= 1) {
        if (t < off) red[t] += red[t + off];
        __syncthreads();
    }
    if (blockIdx.x == 0 && t == 0) g_c = red[0];

    // phase V: 8 rows of v per block (warp per row; warps 8..15 idle)
    const int wp   = t >> 5;
    const int lane = t & 31;
    if (wp < 8) {
        const int h = blockIdx.x * 8 + wp;
        const float4* row4 = (const float4*)(Wx2 + h * 512);
        const float4* r4   = (const float4*)rsh;
        float a = 0.f;
#pragma unroll
        for (int k = lane; k < 128; k += 32) {
            const float4 w = row4[k];
            const float4 r = r4[k];
            a = fmaf(w.x, r.x, fmaf(w.y, r.y, fmaf(w.z, r.z, fmaf(w.w, r.w, a))));
        }
#pragma unroll
        for (int o = 16; o; o >>= 1) a += __shfl_xor_sync(0xffffffffu, a, o);
        if (lane == 0) g_v[h] = a;
    }
}

// ---------------------------------------------------------------------------
// Kernel C: main batch.  256 threads = 8 warps; warp = 64 h (broadcast LDS,
// conflict-free), lane = 4 rows.  Inner loop: fp32 dot3 -> f16x2 packed tanh
// (2 per MUFU op) -> fp32 weighted accumulate.  Grid 512.
// ---------------------------------------------------------------------------
__global__ void __launch_bounds__(256) kernelC(const float* __restrict__ X,
                                               const float* __restrict__ Wx1,
                                               const float* __restrict__ bx1,
                                               float* __restrict__ out, int Bn)
{
    __shared__ float4 wt[512];        // {Wx1[0,h], Wx1[1,h], Wx1[2,h], bx1[h]}
    __shared__ float  vs[512];
    __shared__ __align__(16) float pp[8][128];   // [warp][row-in-block]

    const int t = threadIdx.x;
#pragma unroll
    for (int h = t; h < 512; h += 256) {
        wt[h] = make_float4(Wx1[h], Wx1[512 + h], Wx1[1024 + h], bx1[h]);
        vs[h] = g_v[h];
    }
    __syncthreads();

    const int w    = t >> 5;          // 0..7  (h-split)
    const int lane = t & 31;          // 4 rows per lane
    const int h0   = w << 6;          // 64 h per warp
    const int r0   = blockIdx.x * 128 + lane * 4;

    float xv[12];                     // 4 rows x 3 coords
    if (r0 + 3 < Bn) {
        // r0 multiple of 4 -> byte offset r0*12 is 16B-aligned; 48B contiguous
        const float4* xp = (const float4*)(X + r0 * 3);
#pragma unroll
        for (int q = 0; q < 3; q++) {
            const float4 v4 = xp[q];
            xv[q * 4 + 0] = v4.x; xv[q * 4 + 1] = v4.y;
            xv[q * 4 + 2] = v4.z; xv[q * 4 + 3] = v4.w;
        }
    } else {
#pragma unroll
        for (int q = 0; q < 12; q++) {
            const int gi = r0 * 3 + q;
            xv[q] = (gi < Bn * 3) ? X[gi] : 0.f;
        }
    }

    float a0 = 0.f, a1 = 0.f, a2 = 0.f, a3 = 0.f;
#pragma unroll 8
    for (int hh = 0; hh < 64; hh++) {
        const float4 wv = wt[h0 + hh];    // warp-uniform: broadcast
        const float  vv = vs[h0 + hh];    // broadcast
        const float z0 = fmaf(xv[2],  wv.z, fmaf(xv[1],  wv.y, fmaf(xv[0], wv.x, wv.w)));
        const float z1 = fmaf(xv[5],  wv.z, fmaf(xv[4],  wv.y, fmaf(xv[3], wv.x, wv.w)));
        const float z2 = fmaf(xv[8],  wv.z, fmaf(xv[7],  wv.y, fmaf(xv[6], wv.x, wv.w)));
        const float z3 = fmaf(xv[11], wv.z, fmaf(xv[10], wv.y, fmaf(xv[9], wv.x, wv.w)));
        float t0, t1, t2, t3;
        tanh2(z0, z1, t0, t1);            // one MUFU op, two tanh
        tanh2(z2, z3, t2, t3);
        a0 = fmaf(vv, t0, a0);
        a1 = fmaf(vv, t1, a1);
        a2 = fmaf(vv, t2, a2);
        a3 = fmaf(vv, t3, a3);
    }

    // pp[w][lane*4 .. +3]: one conflict-free STS.128 per thread
    *((float4*)&pp[w][lane * 4]) = make_float4(a0, a1, a2, a3);
    __syncthreads();

    if (t < 128) {
        float s = g_c;
#pragma unroll
        for (int w2 = 0; w2 < 8; w2++) s += pp[w2][t];
        const int oi = blockIdx.x * 128 + t;
        if (oi < Bn) out[oi] = s;
    }
}

// ---------------------------------------------------------------------------
extern "C" void kernel_launch(void* const* d_in, const int* in_sizes, int n_in,
                              void* d_out, int out_size)
{
    const float* input = (const float*)d_in[0];
    const float* eq    = (const float*)d_in[1];
    const float* q0    = (const float*)d_in[2];
    const float* q1    = (const float*)d_in[3];
    const float* q2    = (const float*)d_in[4];
    const float* Wx1   = (const float*)d_in[5];
    const float* bx1   = (const float*)d_in[6];
    const float* Wx2   = (const float*)d_in[7];
    const float* bx2   = (const float*)d_in[8];
    const float* Wq01  = (const float*)d_in[9];
    const float* bq01  = (const float*)d_in[10];
    const float* Wq02  = (const float*)d_in[11];
    const float* bq02  = (const float*)d_in[12];
    const float* Wq11  = (const float*)d_in[13];
    const float* bq11  = (const float*)d_in[14];
    const float* Wq12  = (const float*)d_in[15];
    const float* bq12  = (const float*)d_in[16];
    const float* Wq21  = (const float*)d_in[17];
    const float* bq21  = (const float*)d_in[18];
    const float* Wq22  = (const float*)d_in[19];
    const float* bq22  = (const float*)d_in[20];

    const int N  = in_sizes[2];          // 8192 quad nodes
    const int Bn = in_sizes[0] / 3;      // 65536 rows
    const int nblkA = N / 64;            // 128 chunks of 64 nodes

    kernelA<<<dim3(nblkA, 3), 512>>>(q0, q1, q2,
                                     Wq01, Wq11, Wq21,
                                     bq01, bq11, bq21, eq);
    kernelBV<<<64, 512>>>(Wq02, bq02, Wq12, bq12, Wq22, bq22, bx2, Wx2);
    kernelC<<<(Bn + 127) / 128, 256>>>(input, Wx1, bx1, (float*)d_out, Bn);
}